// round 13
// baseline (speedup 1.0000x reference)
#include <cuda_runtime.h>
#include <cuda_fp16.h>
#include <cstdint>

#define DEV_INLINE __device__ __forceinline__

// ---------------- problem sizes ----------------
static constexpr int kB = 16384;
static constexpr int kD = 1024;
static constexpr int kU = 128;

// ---------------- tiling ----------------
static constexpr int DC    = 32;            // K per chunk
static constexpr int NCH   = kD / DC;       // 32 chunks
static constexpr int PAIRS = 3;             // stream pairs (0,1),(2,3),(4,5); stream0 = x (base)
static constexpr int PAIR_BYTES = 128 * 128;           // 128 rows x 128B
static constexpr int HALF_BUF   = PAIRS * PAIR_BYTES;  // 49152 (A region or W region)
static constexpr int BUF_BYTES  = 2 * HALF_BUF;        // 98304 per buffer
static constexpr int SMEM_TOTAL = 2 * BUF_BYTES;       // 196608 double-buffered

static constexpr int W_HALVES = NCH * PAIRS * 8192;    // 786432 fp16
static constexpr int W_U4_PER_CHUNK = PAIRS * 8192 * 2 / 16;  // 3072 uint4

static constexpr int NTHREADS = 256;  // 8 warps: wid 0-3 producer+baseGEMM, wid 4-7 spline

// prepacked, SW128-swizzled fp16 weights: [chunk32][pair][128 rows][128B (2 streams)]
__device__ __half g_Wpack[W_HALVES];

// ---------------- PTX helpers ----------------
DEV_INLINE uint32_t smem_u32(const void* p) {
    uint32_t a;
    asm("{ .reg .u64 t; cvta.to.shared.u64 t, %1; cvt.u32.u64 %0, t; }" : "=r"(a) : "l"(p));
    return a;
}

#define LDSM_X4(r, addr)                                                        \
    asm volatile("ldmatrix.sync.aligned.m8n8.x4.shared.b16 {%0,%1,%2,%3}, [%4];"\
                 : "=r"((r)[0]), "=r"((r)[1]), "=r"((r)[2]), "=r"((r)[3])       \
                 : "r"(addr))

DEV_INLINE void mma16816(float* d, const uint32_t* a, uint32_t b0, uint32_t b1) {
    asm volatile(
        "mma.sync.aligned.m16n8k16.row.col.f32.f16.f16.f32 "
        "{%0,%1,%2,%3}, {%4,%5,%6,%7}, {%8,%9}, {%0,%1,%2,%3};"
        : "+f"(d[0]), "+f"(d[1]), "+f"(d[2]), "+f"(d[3])
        : "r"(a[0]), "r"(a[1]), "r"(a[2]), "r"(a[3]), "r"(b0), "r"(b1));
}

DEV_INLINE void cp_async16(uint32_t smem_dst, const void* gsrc) {
    asm volatile("cp.async.cg.shared.global [%0], [%1], 16;"
                 :: "r"(smem_dst), "l"(gsrc) : "memory");
}
DEV_INLINE void cp_async_commit() { asm volatile("cp.async.commit_group;" ::: "memory"); }
DEV_INLINE void cp_async_wait_all() { asm volatile("cp.async.wait_group 0;" ::: "memory"); }

// ---------------- weight prep: fp32 -> fp16, pair-interleaved + SW128 ----------------
__global__ void kan_prep_weights(const float* __restrict__ bw,
                                 const float* __restrict__ sw) {
    int idx = blockIdx.x * blockDim.x + threadIdx.x;
    if (idx >= W_HALVES) return;
    int hw  = idx & 63;            // half within 128B row
    int slo = hw >> 5;             // stream half (0/1)
    int k   = hw & 31;             // K within chunk
    int n   = (idx >> 6) & 127;    // output unit (B row)
    int t3  = idx >> 13;           // c*3 + p
    int p   = t3 % 3;
    int c   = t3 / 3;
    int s   = p * 2 + slo;         // stream 0..5 (0 = base weights)
    int i   = c * DC + k;          // feature index
    float v = (s == 0) ? bw[i * kU + n]
                       : sw[(size_t)(i * kU + n) * 8 + (s - 1)];
    unsigned off = (unsigned)(n * 128 + slo * 64 + k * 2);
    unsigned swz = off ^ ((off >> 3) & 0x70);
    g_Wpack[(size_t)t3 * 8192 + (swz >> 1)] = __float2half(v);
}

// ---- 64x64 warp-tile fragment load (stream s_, k-step kk_) ----
#define LD64x64(S, KK, FA, FB) do {                                             \
    constexpr uint32_t pOff_ = (uint32_t)(((S) >> 1) * PAIR_BYTES);             \
    constexpr uint32_t kb_   = (uint32_t)(((S) & 1) * 64 + (KK) * 32);          \
    LDSM_X4(&(FB)[0],  bBase + pOff_ + bOff0 + ((kb_ + 0u)  ^ bXor0));          \
    LDSM_X4(&(FB)[4],  bBase + pOff_ + bOff0 + ((kb_ + 16u) ^ bXor0));          \
    LDSM_X4(&(FB)[8],  bBase + pOff_ + bOff1 + ((kb_ + 0u)  ^ bXor1));          \
    LDSM_X4(&(FB)[12], bBase + pOff_ + bOff1 + ((kb_ + 16u) ^ bXor1));          \
    {                                                                           \
        const uint32_t kbA_ = kb_ + kbAhi;                                      \
        _Pragma("unroll")                                                       \
        for (int mb_ = 0; mb_ < 4; ++mb_)                                       \
            LDSM_X4(&(FA)[mb_ * 4],                                             \
                    aBase + pOff_ + aOff[mb_] + (kbA_ ^ aXor[mb_]));            \
    }                                                                           \
} while (0)

#define MMA64x64(FA, FB) do {                                                   \
    _Pragma("unroll")                                                           \
    for (int mb_ = 0; mb_ < 4; ++mb_)                                           \
        _Pragma("unroll")                                                       \
        for (int bh_ = 0; bh_ < 2; ++bh_)                                       \
            _Pragma("unroll")                                                   \
            for (int nbi_ = 0; nbi_ < 4; ++nbi_)                                \
                mma16816(acc[mb_][bh_ * 4 + nbi_], &(FA)[mb_ * 4],              \
                         (FB)[bh_ * 8 + nbi_], (FB)[bh_ * 8 + 4 + nbi_]);       \
} while (0)

// ---------------- main fused kernel ----------------
__global__ void __launch_bounds__(NTHREADS, 1)
kan_main_kernel(const float* __restrict__ x, float* __restrict__ out) {
    extern __shared__ char smem[];
    const uint32_t smem_base = smem_u32(smem);
    const int tid  = threadIdx.x;
    const int wid  = tid >> 5;
    const int lane = tid & 31;
    const int row_base = blockIdx.x * 128;

    // 2x2 grid of 64x64 tiles; both warp groups use the same mapping
    const int w  = wid & 3;
    const int mi = w & 1;
    const int ni = w >> 1;

    float acc[4][8][4];
    #pragma unroll
    for (int a = 0; a < 4; ++a)
        #pragma unroll
        for (int b = 0; b < 8; ++b)
            #pragma unroll
            for (int j = 0; j < 4; ++j) acc[a][b][j] = 0.f;

    // fragment addressing (buffer 0 base; per-chunk aBase/bBase toggle)
    const int aRowLocal  = (lane & 7) + ((lane >> 3) & 1) * 8;
    const uint32_t kbAhi = ((lane >> 4) & 1) * 16;
    uint32_t aOff[4], aXor[4];
    #pragma unroll
    for (int mb = 0; mb < 4; ++mb) {
        int r = mi * 64 + mb * 16 + aRowLocal;
        aOff[mb] = (uint32_t)(r * 128);
        aXor[mb] = (uint32_t)((r & 7) << 4);
    }
    const int rB0 = ni * 64 + lane;          // bh = 0
    const int rB1 = ni * 64 + 32 + lane;     // bh = 1
    const uint32_t bOff0 = (uint32_t)(rB0 * 128);
    const uint32_t bXor0 = (uint32_t)((rB0 & 7) << 4);
    const uint32_t bOff1 = (uint32_t)(rB1 * 128);
    const uint32_t bXor1 = (uint32_t)((rB1 & 7) << 4);

    const float E375p = 42.52108200006278f;    // e^{3.75}
    const float E125p = 3.4903429574597902f;   // e^{1.25}
    const float E125m = 0.2865047968601901f;   // e^{-1.25}
    const float E375m = 0.023517745856009107f; // e^{-3.75}

    if (wid < 4) {
        // ============ PRODUCER + BASE-GEMM warps (wid 0-3, 128 threads) ============
        const int pr = tid;                        // row 0..127
        const float* xp = x + (size_t)(row_base + pr) * kD;
        const uint32_t aSw = (uint32_t)((pr & 7) << 4);

        auto produce = [&](int c, uint32_t aRegionOff) {
            const float* xc = xp + c * DC;
            float4 xq[8];
            #pragma unroll
            for (int j = 0; j < 8; ++j)
                xq[j] = *reinterpret_cast<const float4*>(xc + j * 4);
            #pragma unroll
            for (int g = 0; g < 4; ++g) {
                float xs[8];
                xs[0]=xq[2*g].x;   xs[1]=xq[2*g].y;   xs[2]=xq[2*g].z;   xs[3]=xq[2*g].w;
                xs[4]=xq[2*g+1].x; xs[5]=xq[2*g+1].y; xs[6]=xq[2*g+1].z; xs[7]=xq[2*g+1].w;
                union { __half2 h2[4]; uint4 u4; } st[6];
                #pragma unroll
                for (int e = 0; e < 8; e += 2) {
                    float a0 = xs[e] + 1.f, a1 = xs[e+1] + 1.f;
                    float y0a = __expf(-5.f * a0 * a0);
                    float y0b = __expf(-5.f * a1 * a1);
                    float ta  = __expf(5.f * xs[e]);
                    float tb  = __expf(5.f * xs[e+1]);
                    float y1a = y0a * ta * E375p, y1b = y0b * tb * E375p;
                    float y2a = y1a * ta * E125p, y2b = y1b * tb * E125p;
                    float y3a = y2a * ta * E125m, y3b = y2b * tb * E125m;
                    float y4a = y3a * ta * E375m, y4b = y3b * tb * E375m;
                    int j = e >> 1;
                    st[0].h2[j] = __floats2half2_rn(xs[e], xs[e+1]);
                    st[1].h2[j] = __floats2half2_rn(y0a, y0b);
                    st[2].h2[j] = __floats2half2_rn(y1a, y1b);
                    st[3].h2[j] = __floats2half2_rn(y2a, y2b);
                    st[4].h2[j] = __floats2half2_rn(y3a, y3b);
                    st[5].h2[j] = __floats2half2_rn(y4a, y4b);
                }
                #pragma unroll
                for (int s = 0; s < 6; ++s) {
                    int p = s >> 1, slo = s & 1;
                    unsigned off = (unsigned)(pr * 128 + slo * 64 + g * 16);
                    unsigned swz = off ^ aSw;
                    *reinterpret_cast<uint4*>(smem + aRegionOff + p * PAIR_BYTES + swz)
                        = st[s].u4;
                }
            }
        };

        auto copyW = [&](int c, uint32_t wRegion) {
            const char* src = reinterpret_cast<const char*>(g_Wpack) +
                              (size_t)c * (PAIRS * 8192 * 2);
            #pragma unroll
            for (int j = 0; j < W_U4_PER_CHUNK / 128; ++j) {  // 24 per thread
                int i = pr + j * 128;
                cp_async16(wRegion + i * 16, src + i * 16);
            }
            cp_async_commit();
        };

        // prologue: chunk 0 -> buffer 0
        copyW(0, smem_base + HALF_BUF);
        produce(0, 0);
        cp_async_wait_all();
        __syncthreads();

        for (int c = 0; c < NCH; ++c) {
            if (c + 1 < NCH) {
                const uint32_t bufOff = (uint32_t)(((c + 1) & 1) * BUF_BYTES);
                copyW(c + 1, smem_base + bufOff + HALF_BUF);
                produce(c + 1, bufOff);
            }
            // base GEMM on chunk c: stream 0 (pair 0, slo 0), 2 k16-steps
            {
                const uint32_t aBase = smem_base + (uint32_t)((c & 1) * BUF_BYTES);
                const uint32_t bBase = aBase + (uint32_t)HALF_BUF;
                uint32_t fa0[16], fb0[16], fa1[16], fb1[16];
                LD64x64(0, 0, fa0, fb0);
                LD64x64(0, 1, fa1, fb1);
                MMA64x64(fa0, fb0);
                MMA64x64(fa1, fb1);
            }
            cp_async_wait_all();
            __syncthreads();
        }

        // epilogue part 1: SiLU(base) -> smem exchange (fp32, row-major 128x128)
        {
            float* exch = reinterpret_cast<float*>(smem);
            const int colBase = ni * 64 + (lane & 3) * 2;
            #pragma unroll
            for (int mb = 0; mb < 4; ++mb) {
                int r0 = mi * 64 + mb * 16 + (lane >> 2);
                #pragma unroll
                for (int nb = 0; nb < 8; ++nb) {
                    int col = colBase + (nb >> 2) * 32 + (nb & 3) * 8;
                    float z0 = acc[mb][nb][0], z1 = acc[mb][nb][1];
                    float z2 = acc[mb][nb][2], z3 = acc[mb][nb][3];
                    float2 v0, v1;
                    v0.x = __fdividef(z0, 1.f + __expf(-z0));
                    v0.y = __fdividef(z1, 1.f + __expf(-z1));
                    v1.x = __fdividef(z2, 1.f + __expf(-z2));
                    v1.y = __fdividef(z3, 1.f + __expf(-z3));
                    *reinterpret_cast<float2*>(exch + r0 * 128 + col)       = v0;
                    *reinterpret_cast<float2*>(exch + (r0 + 8) * 128 + col) = v1;
                }
            }
        }
        __syncthreads();
    } else {
        // ============ SPLINE consumer warps (wid 4-7, hi-wid priority) ============
        __syncthreads();  // matches producer prologue sync

        uint32_t fa0[16], fa1[16], fb0[16], fb1[16];
        for (int c = 0; c < NCH; ++c) {
            const uint32_t aBase = smem_base + (uint32_t)((c & 1) * BUF_BYTES);
            const uint32_t bBase = aBase + (uint32_t)HALF_BUF;
            // streams 1..5, 2 k-steps each: 10 steps, fragment-pipelined
            LD64x64(1, 0, fa0, fb0);
            LD64x64(1, 1, fa1, fb1);  MMA64x64(fa0, fb0);
            LD64x64(2, 0, fa0, fb0);  MMA64x64(fa1, fb1);
            LD64x64(2, 1, fa1, fb1);  MMA64x64(fa0, fb0);
            LD64x64(3, 0, fa0, fb0);  MMA64x64(fa1, fb1);
            LD64x64(3, 1, fa1, fb1);  MMA64x64(fa0, fb0);
            LD64x64(4, 0, fa0, fb0);  MMA64x64(fa1, fb1);
            LD64x64(4, 1, fa1, fb1);  MMA64x64(fa0, fb0);
            LD64x64(5, 0, fa0, fb0);  MMA64x64(fa1, fb1);
            LD64x64(5, 1, fa1, fb1);  MMA64x64(fa0, fb0);
                                      MMA64x64(fa1, fb1);
            __syncthreads();
        }

        // epilogue part 2: read SiLU(base) from exchange, add spline, store
        __syncthreads();  // wait for base warps' exchange stores
        {
            const float* exch = reinterpret_cast<const float*>(smem);
            const int colBase = ni * 64 + (lane & 3) * 2;
            #pragma unroll
            for (int mb = 0; mb < 4; ++mb) {
                int rloc = mi * 64 + mb * 16 + (lane >> 2);
                int row0 = row_base + rloc;
                #pragma unroll
                for (int nb = 0; nb < 8; ++nb) {
                    int col = colBase + (nb >> 2) * 32 + (nb & 3) * 8;
                    float2 b0 = *reinterpret_cast<const float2*>(exch + rloc * 128 + col);
                    float2 b1 = *reinterpret_cast<const float2*>(exch + (rloc + 8) * 128 + col);
                    float2 v0, v1;
                    v0.x = b0.x + acc[mb][nb][0]; v0.y = b0.y + acc[mb][nb][1];
                    v1.x = b1.x + acc[mb][nb][2]; v1.y = b1.y + acc[mb][nb][3];
                    *reinterpret_cast<float2*>(out + (size_t)row0 * kU + col)       = v0;
                    *reinterpret_cast<float2*>(out + (size_t)(row0 + 8) * kU + col) = v1;
                }
            }
        }
    }
}

// ---------------- launch ----------------
extern "C" void kernel_launch(void* const* d_in, const int* in_sizes, int n_in,
                              void* d_out, int out_size) {
    (void)in_sizes; (void)n_in; (void)out_size;
    const float* x  = (const float*)d_in[0];
    const float* bw = (const float*)d_in[1];
    const float* sw = (const float*)d_in[2];
    float* out = (float*)d_out;

    cudaFuncSetAttribute(kan_main_kernel,
                         cudaFuncAttributeMaxDynamicSharedMemorySize, SMEM_TOTAL);

    kan_prep_weights<<<(W_HALVES + 255) / 256, 256>>>(bw, sw);
    kan_main_kernel<<<kB / 128, NTHREADS, SMEM_TOTAL>>>(x, out);
}